// round 9
// baseline (speedup 1.0000x reference)
#include <cuda_runtime.h>
#include <cuda_bf16.h>

// Lp_Conv2D_BT: out[b,o,i,j] = max_{k<4} | w[o,k] - x_pad[b, c_k, i+di_k-1, j+dj_k-1] | + bias[o]
// edge padding (clamp), stride 1.
// x:(32,64,64,64) f32; weights:(128,4) f32; bias:(128,1,1) f32; conn_idx:(128,4) i32.
// out:(32,128,64,64) f32.

namespace {
constexpr int HW   = 64;
constexpr int CIN  = 64;
constexpr int COUT = 128;
constexpr int CONN = 4;
}

__global__ __launch_bounds__(256, 8) void lp_conv_bt_kernel(
    const float* __restrict__ x,
    const float* __restrict__ weights,
    const float* __restrict__ bias,
    const int*   __restrict__ conn_idx,
    float*       __restrict__ out)
{
    const int blk = blockIdx.x;          // blk = b*COUT + o
    const int o   = blk & (COUT - 1);
    const int b   = blk >> 7;
    const int t   = threadIdx.x;

    const int lane16 = t & 15;
    const int r0     = t >> 4;           // 0..15
    const bool laneLo = (lane16 == 0);
    const bool laneHi = (lane16 == 15);

    const float* xb = x + (size_t)b * CIN * (HW * HW);

    // Per-output-channel connection parameters (uniform across the block).
    const float* bp[CONN];
    int a0[CONN], a3[CONN], dc[CONN];
    float w[CONN];
#pragma unroll
    for (int k = 0; k < CONN; ++k) {
        const int idx = __ldg(conn_idx + o * CONN + k);   // [0, 576)
        const int c   = idx / 9;
        const int rem = idx - c * 9;
        const int di  = rem / 3;
        const int drk = di - 1;                            // {-1,0,1}
        dc[k] = (rem - di * 3) - 1;                        // {-1,0,1}
        w[k]  = __ldg(weights + o * CONN + k);
        bp[k] = xb + c * (HW * HW) + (r0 + drk) * HW + lane16 * 4;
        a0[k] = ((r0 + drk) < 0) ? HW : 0;                 // only r0==0, dr==-1
        a3[k] = ((r0 + 48 + drk) > HW - 1) ? -HW : 0;      // only r0==15, dr==+1
    }
    const float bs = __ldg(bias + o);

    // 16 max-accumulators: m[rb][j], all >= 0.
    float m[4][4];
#pragma unroll
    for (int rb = 0; rb < 4; ++rb)
#pragma unroll
        for (int j = 0; j < 4; ++j) m[rb][j] = 0.f;

    // k outer: 4 loads, ONE uniform dc branch, then 4 straight-line
    // row-block accumulates inside the taken arm.
#pragma unroll
    for (int k = 0; k < CONN; ++k) {
        float4 v[4];
        v[0] = __ldg(reinterpret_cast<const float4*>(bp[k] + a0[k]));
        v[1] = __ldg(reinterpret_cast<const float4*>(bp[k] + 16 * HW));
        v[2] = __ldg(reinterpret_cast<const float4*>(bp[k] + 32 * HW));
        v[3] = __ldg(reinterpret_cast<const float4*>(bp[k] + 48 * HW + a3[k]));
        const float wk = w[k];

        if (dc[k] == 0) {
#pragma unroll
            for (int rb = 0; rb < 4; ++rb) {
                m[rb][0] = fmaxf(m[rb][0], fabsf(wk - v[rb].x));
                m[rb][1] = fmaxf(m[rb][1], fabsf(wk - v[rb].y));
                m[rb][2] = fmaxf(m[rb][2], fabsf(wk - v[rb].z));
                m[rb][3] = fmaxf(m[rb][3], fabsf(wk - v[rb].w));
            }
        } else if (dc[k] > 0) {
#pragma unroll
            for (int rb = 0; rb < 4; ++rb) {
                // cols j0+1..j0+4 ; j0+4 = next lane's v.x (col 64 -> clamp 63 = v.w)
                float e = __shfl_down_sync(0xffffffffu, v[rb].x, 1, 16);
                if (laneHi) e = v[rb].w;
                m[rb][0] = fmaxf(m[rb][0], fabsf(wk - v[rb].y));
                m[rb][1] = fmaxf(m[rb][1], fabsf(wk - v[rb].z));
                m[rb][2] = fmaxf(m[rb][2], fabsf(wk - v[rb].w));
                m[rb][3] = fmaxf(m[rb][3], fabsf(wk - e));
            }
        } else {
#pragma unroll
            for (int rb = 0; rb < 4; ++rb) {
                // cols j0-1..j0+2 ; j0-1 = prev lane's v.w (col -1 -> clamp 0 = v.x)
                float e = __shfl_up_sync(0xffffffffu, v[rb].w, 1, 16);
                if (laneLo) e = v[rb].x;
                m[rb][0] = fmaxf(m[rb][0], fabsf(wk - e));
                m[rb][1] = fmaxf(m[rb][1], fabsf(wk - v[rb].x));
                m[rb][2] = fmaxf(m[rb][2], fabsf(wk - v[rb].y));
                m[rb][3] = fmaxf(m[rb][3], fabsf(wk - v[rb].z));
            }
        }
    }

    // Epilogue: bias + streaming float4 stores (contiguous per lane).
    float4* po = reinterpret_cast<float4*>(out + (size_t)blk * (HW * HW)) + r0 * 16 + lane16;
#pragma unroll
    for (int rb = 0; rb < 4; ++rb) {
        __stcs(po + rb * 16 * 16,
               make_float4(m[rb][0] + bs, m[rb][1] + bs, m[rb][2] + bs, m[rb][3] + bs));
    }
}

extern "C" void kernel_launch(void* const* d_in, const int* in_sizes, int n_in,
                              void* d_out, int out_size) {
    const float* x       = (const float*)d_in[0];
    const float* weights = (const float*)d_in[1];
    const float* bias    = (const float*)d_in[2];
    const int*   conn    = (const int*)d_in[3];
    float*       out     = (float*)d_out;

    const int B = in_sizes[0] / (CIN * HW * HW);   // 32
    lp_conv_bt_kernel<<<B * COUT, 256>>>(x, weights, bias, conn, out);
}

// round 10
// speedup vs baseline: 1.1511x; 1.1511x over previous
#include <cuda_runtime.h>
#include <cuda_bf16.h>

// Lp_Conv2D_BT via smem staging:
// out[b,o,i,j] = max_{k<4} | w[o,k] - x_pad[b, c_k, i+di_k-1, j+dj_k-1] | + bias[o]
// CTA = one batch b, one 4-row strip, ALL 128 output channels.
// Stage x[b, all ch, strip rows + row halo, cols + col halo] in smem with edge
// clamp applied at staging; per-o conn params become pure smem byte offsets.
// Hot loop: branch-free scalar LDS gathers (lane==col -> conflict-free).

namespace {
constexpr int HW        = 64;
constexpr int CIN       = 64;
constexpr int COUT      = 128;
constexpr int CONN      = 4;
constexpr int ROWS_OUT  = 4;                         // output rows per CTA
constexpr int ROWS_ST   = ROWS_OUT + 2;              // staged rows (halo)
constexpr int ROW_STRIDE = 288;                      // bytes per staged row
constexpr int COL0      = 16;                        // byte offset of col 0 (4 pad floats -> float4-aligned stores)
constexpr int CH_STRIDE = ROWS_ST * ROW_STRIDE;      // 1728 B per channel
constexpr int X_BYTES   = CIN * CH_STRIDE;           // 110592
constexpr int OFF_PAR   = X_BYTES;                   // int4 per o  (gather offsets)
constexpr int W_PAR     = OFF_PAR + COUT * 16;       // float4 per o (weights)
constexpr int B_PAR     = W_PAR + COUT * 16;         // float per o (bias)
constexpr int SMEM_TOTAL = B_PAR + COUT * 4;         // 115200 B
}

__global__ __launch_bounds__(256) void lp_conv_bt_kernel(
    const float* __restrict__ x,
    const float* __restrict__ weights,
    const float* __restrict__ bias,
    const int*   __restrict__ conn_idx,
    float*       __restrict__ out)
{
    extern __shared__ unsigned char smem[];

    const int bx    = blockIdx.x;        // bx = b*16 + strip
    const int b     = bx >> 4;
    const int strip = bx & 15;
    const int rbase = strip * ROWS_OUT;
    const int t     = threadIdx.x;

    const float* xb = x + (size_t)b * CIN * (HW * HW);

    // ---- Stage main tile: 64 ch x 6 rows x 64 cols (float4, coalesced) ----
#pragma unroll
    for (int it = 0; it < 24; ++it) {
        const int idx = t + it * 256;            // 0..6143 float4s
        const int ch  = idx / 96;                // 96 float4 per channel
        const int rem = idx - ch * 96;
        const int i   = rem >> 4;                // staged row 0..5
        const int c4  = rem & 15;
        const int srow = min(max(rbase + i - 1, 0), HW - 1);   // edge row clamp
        const float4 v = __ldg(reinterpret_cast<const float4*>(
            xb + ch * (HW * HW) + srow * HW + c4 * 4));
        *reinterpret_cast<float4*>(smem + ch * CH_STRIDE + i * ROW_STRIDE
                                   + COL0 + c4 * 16) = v;
    }

    // ---- Column halos: col -1 (=col 0) and col 64 (=col 63), 768 entries ----
#pragma unroll
    for (int p = 0; p < 3; ++p) {
        const int e    = t + p * 256;            // 0..767
        const int ch   = e / 12;
        const int rem  = e - ch * 12;
        const int i    = rem >> 1;
        const int side = rem & 1;
        const int srow = min(max(rbase + i - 1, 0), HW - 1);
        const float v  = __ldg(xb + ch * (HW * HW) + srow * HW + (side ? HW - 1 : 0));
        *reinterpret_cast<float*>(smem + ch * CH_STRIDE + i * ROW_STRIDE
                                  + (side ? COL0 + HW * 4 : COL0 - 4)) = v;
    }

    // ---- Per-o params: smem byte offsets with dr/dc folded in ----
    if (t < COUT) {
        int4   offs;
        float4 wv;
        int* po = &offs.x;
        float* pw = &wv.x;
#pragma unroll
        for (int k = 0; k < CONN; ++k) {
            const int idx = __ldg(conn_idx + t * CONN + k);  // [0,576)
            const int c   = idx / 9;
            const int rem = idx - c * 9;
            const int di  = rem / 3;                          // staged-row delta (dr+1)
            const int dj  = rem - di * 3;                     // dc+1
            po[k] = c * CH_STRIDE + di * ROW_STRIDE + (dj - 1) * 4;
            pw[k] = __ldg(weights + t * CONN + k);
        }
        *reinterpret_cast<int4*>(smem + OFF_PAR + t * 16)  = offs;
        *reinterpret_cast<float4*>(smem + W_PAR + t * 16)  = wv;
        *reinterpret_cast<float*>(smem + B_PAR + t * 4)    = __ldg(bias + t);
    }

    __syncthreads();

    // ---- Compute: warp covers (o, row); lane = col (+32). Branch-free. ----
    const int warp = t >> 5;
    const int lane = t & 31;
    unsigned char* const gbase = smem + COL0 + lane * 4;

    for (int oo = 0; oo < 16; ++oo) {
        const int o = warp * 16 + oo;
        const int4   offs = *reinterpret_cast<const int4*>(smem + OFF_PAR + o * 16);
        const float4 wv   = *reinterpret_cast<const float4*>(smem + W_PAR + o * 16);
        const float  bs   = *reinterpret_cast<const float*>(smem + B_PAR + o * 4);

        const float* g0 = reinterpret_cast<const float*>(gbase + offs.x);
        const float* g1 = reinterpret_cast<const float*>(gbase + offs.y);
        const float* g2 = reinterpret_cast<const float*>(gbase + offs.z);
        const float* g3 = reinterpret_cast<const float*>(gbase + offs.w);

        float* po = out + ((size_t)(b * COUT + o) * (HW * HW)) + rbase * HW + lane;

#pragma unroll
        for (int r = 0; r < ROWS_OUT; ++r) {
            const int ro = r * (ROW_STRIDE / 4);             // 72 floats per row
            // jj = 0 (cols lane)
            float m0 = fabsf(wv.x - g0[ro]);
            m0 = fmaxf(m0, fabsf(wv.y - g1[ro]));
            m0 = fmaxf(m0, fabsf(wv.z - g2[ro]));
            m0 = fmaxf(m0, fabsf(wv.w - g3[ro]));
            // jj = 1 (cols lane+32)
            float m1 = fabsf(wv.x - g0[ro + 32]);
            m1 = fmaxf(m1, fabsf(wv.y - g1[ro + 32]));
            m1 = fmaxf(m1, fabsf(wv.z - g2[ro + 32]));
            m1 = fmaxf(m1, fabsf(wv.w - g3[ro + 32]));

            __stcs(po + r * HW,      m0 + bs);
            __stcs(po + r * HW + 32, m1 + bs);
        }
    }
}

extern "C" void kernel_launch(void* const* d_in, const int* in_sizes, int n_in,
                              void* d_out, int out_size) {
    const float* x       = (const float*)d_in[0];
    const float* weights = (const float*)d_in[1];
    const float* bias    = (const float*)d_in[2];
    const int*   conn    = (const int*)d_in[3];
    float*       out     = (float*)d_out;

    cudaFuncSetAttribute(lp_conv_bt_kernel,
                         cudaFuncAttributeMaxDynamicSharedMemorySize, SMEM_TOTAL);

    const int B = in_sizes[0] / (CIN * HW * HW);   // 32
    lp_conv_bt_kernel<<<B * 16, 256, SMEM_TOTAL>>>(x, weights, bias, conn, out);
}

// round 11
// speedup vs baseline: 1.1790x; 1.0242x over previous
#include <cuda_runtime.h>
#include <cuda_bf16.h>

// Lp_Conv2D_BT via smem staging (R10 dataflow, 512-thread CTAs for occupancy):
// out[b,o,i,j] = max_{k<4} | w[o,k] - x_pad[b, c_k, i+di_k-1, j+dj_k-1] | + bias[o]
// CTA = one batch b, one 4-row strip, ALL 128 output channels.

namespace {
constexpr int HW        = 64;
constexpr int CIN       = 64;
constexpr int COUT      = 128;
constexpr int CONN      = 4;
constexpr int ROWS_OUT  = 4;
constexpr int ROWS_ST   = ROWS_OUT + 2;
constexpr int ROW_STRIDE = 288;                      // bytes per staged row
constexpr int COL0      = 16;                        // byte offset of col 0
constexpr int CH_STRIDE = ROWS_ST * ROW_STRIDE;      // 1728 B per channel
constexpr int X_BYTES   = CIN * CH_STRIDE;           // 110592
constexpr int OFF_PAR   = X_BYTES;                   // int4 per o
constexpr int W_PAR     = OFF_PAR + COUT * 16;       // float4 per o
constexpr int B_PAR     = W_PAR + COUT * 16;         // float per o
constexpr int SMEM_TOTAL = B_PAR + COUT * 4;         // 115200 B -> 2 CTAs/SM
constexpr int NT        = 512;                       // 16 warps
}

__global__ __launch_bounds__(NT, 2) void lp_conv_bt_kernel(
    const float* __restrict__ x,
    const float* __restrict__ weights,
    const float* __restrict__ bias,
    const int*   __restrict__ conn_idx,
    float*       __restrict__ out)
{
    extern __shared__ unsigned char smem[];

    const int bx    = blockIdx.x;        // bx = b*16 + strip
    const int b     = bx >> 4;
    const int strip = bx & 15;
    const int rbase = strip * ROWS_OUT;
    const int t     = threadIdx.x;

    const float* xb = x + (size_t)b * CIN * (HW * HW);

    // ---- Stage main tile: 64 ch x 6 rows x 64 cols (float4, coalesced) ----
#pragma unroll
    for (int it = 0; it < 12; ++it) {
        const int idx = t + it * NT;             // 0..6143 float4s
        const int ch  = idx / 96;                // 96 float4 per channel
        const int rem = idx - ch * 96;
        const int i   = rem >> 4;                // staged row 0..5
        const int c4  = rem & 15;
        const int srow = min(max(rbase + i - 1, 0), HW - 1);   // edge row clamp
        const float4 v = __ldg(reinterpret_cast<const float4*>(
            xb + ch * (HW * HW) + srow * HW + c4 * 4));
        *reinterpret_cast<float4*>(smem + ch * CH_STRIDE + i * ROW_STRIDE
                                   + COL0 + c4 * 16) = v;
    }

    // ---- Column halos: col -1 (=col 0) and col 64 (=col 63), 768 entries ----
#pragma unroll
    for (int p = 0; p < 2; ++p) {
        const int e = t + p * NT;                // 0..1023, guard at 768
        if (e < CIN * ROWS_ST * 2) {
            const int ch   = e / 12;
            const int rem  = e - ch * 12;
            const int i    = rem >> 1;
            const int side = rem & 1;
            const int srow = min(max(rbase + i - 1, 0), HW - 1);
            const float v  = __ldg(xb + ch * (HW * HW) + srow * HW + (side ? HW - 1 : 0));
            *reinterpret_cast<float*>(smem + ch * CH_STRIDE + i * ROW_STRIDE
                                      + (side ? COL0 + HW * 4 : COL0 - 4)) = v;
        }
    }

    // ---- Per-o params: smem byte offsets with dr/dc folded in ----
    if (t < COUT) {
        int4   offs;
        float4 wv;
        int* po = &offs.x;
        float* pw = &wv.x;
#pragma unroll
        for (int k = 0; k < CONN; ++k) {
            const int idx = __ldg(conn_idx + t * CONN + k);  // [0,576)
            const int c   = idx / 9;
            const int rem = idx - c * 9;
            const int di  = rem / 3;                          // staged-row delta
            const int dj  = rem - di * 3;
            po[k] = c * CH_STRIDE + di * ROW_STRIDE + (dj - 1) * 4;
            pw[k] = __ldg(weights + t * CONN + k);
        }
        *reinterpret_cast<int4*>(smem + OFF_PAR + t * 16)  = offs;
        *reinterpret_cast<float4*>(smem + W_PAR + t * 16)  = wv;
        *reinterpret_cast<float*>(smem + B_PAR + t * 4)    = __ldg(bias + t);
    }

    __syncthreads();

    // ---- Compute: 16 warps x 8 o's; lane = col (+32). Branch-free. ----
    const int warp = t >> 5;                     // 0..15
    const int lane = t & 31;
    unsigned char* const gbase = smem + COL0 + lane * 4;

#pragma unroll
    for (int oo = 0; oo < 8; ++oo) {
        const int o = warp * 8 + oo;
        const int4   offs = *reinterpret_cast<const int4*>(smem + OFF_PAR + o * 16);
        const float4 wv   = *reinterpret_cast<const float4*>(smem + W_PAR + o * 16);
        const float  bs   = *reinterpret_cast<const float*>(smem + B_PAR + o * 4);

        const float* g0 = reinterpret_cast<const float*>(gbase + offs.x);
        const float* g1 = reinterpret_cast<const float*>(gbase + offs.y);
        const float* g2 = reinterpret_cast<const float*>(gbase + offs.z);
        const float* g3 = reinterpret_cast<const float*>(gbase + offs.w);

        float* po = out + ((size_t)(b * COUT + o) * (HW * HW)) + rbase * HW + lane;

#pragma unroll
        for (int r = 0; r < ROWS_OUT; ++r) {
            const int ro = r * (ROW_STRIDE / 4);             // 72 floats per row
            float m0 = fabsf(wv.x - g0[ro]);
            m0 = fmaxf(m0, fabsf(wv.y - g1[ro]));
            m0 = fmaxf(m0, fabsf(wv.z - g2[ro]));
            m0 = fmaxf(m0, fabsf(wv.w - g3[ro]));

            float m1 = fabsf(wv.x - g0[ro + 32]);
            m1 = fmaxf(m1, fabsf(wv.y - g1[ro + 32]));
            m1 = fmaxf(m1, fabsf(wv.z - g2[ro + 32]));
            m1 = fmaxf(m1, fabsf(wv.w - g3[ro + 32]));

            __stcs(po + r * HW,      m0 + bs);
            __stcs(po + r * HW + 32, m1 + bs);
        }
    }
}

extern "C" void kernel_launch(void* const* d_in, const int* in_sizes, int n_in,
                              void* d_out, int out_size) {
    const float* x       = (const float*)d_in[0];
    const float* weights = (const float*)d_in[1];
    const float* bias    = (const float*)d_in[2];
    const int*   conn    = (const int*)d_in[3];
    float*       out     = (float*)d_out;

    cudaFuncSetAttribute(lp_conv_bt_kernel,
                         cudaFuncAttributeMaxDynamicSharedMemorySize, SMEM_TOTAL);

    const int B = in_sizes[0] / (CIN * HW * HW);   // 32
    lp_conv_bt_kernel<<<B * 16, NT, SMEM_TOTAL>>>(x, weights, bias, conn, out);
}

// round 12
// speedup vs baseline: 1.3579x; 1.1518x over previous
#include <cuda_runtime.h>
#include <cuda_bf16.h>

// Lp_Conv2D_BT: out[b,o,i,j] = max_{k<4} | w[o,k] - x_pad[b, c_k, i+di_k-1, j+dj_k-1] | + bias[o]
// edge padding (clamp), stride 1.
// x:(32,64,64,64) f32; weights:(128,4) f32; bias:(128,1,1) f32; conn_idx:(128,4) i32.
// out:(32,128,64,64) f32.
// R12: R8 dataflow + double-buffered k-loop loads (MLP 8/warp), 4 CTAs/SM.

namespace {
constexpr int HW   = 64;
constexpr int CIN  = 64;
constexpr int COUT = 128;
constexpr int CONN = 4;
}

__global__ __launch_bounds__(256, 4) void lp_conv_bt_kernel(
    const float* __restrict__ x,
    const float* __restrict__ weights,
    const float* __restrict__ bias,
    const int*   __restrict__ conn_idx,
    float*       __restrict__ out)
{
    const int blk = blockIdx.x;          // blk = b*COUT + o
    const int o   = blk & (COUT - 1);
    const int b   = blk >> 7;
    const int t   = threadIdx.x;

    const int lane16 = t & 15;
    const int r0     = t >> 4;           // 0..15
    const bool laneLo = (lane16 == 0);
    const bool laneHi = (lane16 == 15);

    const float* xb = x + (size_t)b * CIN * (HW * HW);

    // Per-output-channel connection parameters (uniform across the block).
    const float* bp[CONN];
    int a0[CONN], a3[CONN], dc[CONN];
    float w[CONN];
#pragma unroll
    for (int k = 0; k < CONN; ++k) {
        const int idx = __ldg(conn_idx + o * CONN + k);   // [0, 576)
        const int c   = idx / 9;
        const int rem = idx - c * 9;
        const int di  = rem / 3;
        const int drk = di - 1;                            // {-1,0,1}
        dc[k] = (rem - di * 3) - 1;                        // {-1,0,1}
        w[k]  = __ldg(weights + o * CONN + k);
        bp[k] = xb + c * (HW * HW) + (r0 + drk) * HW + lane16 * 4;
        a0[k] = ((r0 + drk) < 0) ? HW : 0;                 // only r0==0, dr==-1
        a3[k] = ((r0 + 48 + drk) > HW - 1) ? -HW : 0;      // only r0==15, dr==+1
    }
    const float bs = __ldg(bias + o);

    // 16 max-accumulators: m[rb][j], all >= 0.
    float m[4][4];
#pragma unroll
    for (int rb = 0; rb < 4; ++rb)
#pragma unroll
        for (int j = 0; j < 4; ++j) m[rb][j] = 0.f;

    auto load4 = [&](float4* v, int k) {
        v[0] = __ldg(reinterpret_cast<const float4*>(bp[k] + a0[k]));
        v[1] = __ldg(reinterpret_cast<const float4*>(bp[k] + 16 * HW));
        v[2] = __ldg(reinterpret_cast<const float4*>(bp[k] + 32 * HW));
        v[3] = __ldg(reinterpret_cast<const float4*>(bp[k] + 48 * HW + a3[k]));
    };

    auto consume = [&](const float4* v, int k) {
        const float wk = w[k];
        if (dc[k] == 0) {
#pragma unroll
            for (int rb = 0; rb < 4; ++rb) {
                m[rb][0] = fmaxf(m[rb][0], fabsf(wk - v[rb].x));
                m[rb][1] = fmaxf(m[rb][1], fabsf(wk - v[rb].y));
                m[rb][2] = fmaxf(m[rb][2], fabsf(wk - v[rb].z));
                m[rb][3] = fmaxf(m[rb][3], fabsf(wk - v[rb].w));
            }
        } else if (dc[k] > 0) {
#pragma unroll
            for (int rb = 0; rb < 4; ++rb) {
                // cols j0+1..j0+4 ; j0+4 = next lane's v.x (col 64 -> clamp 63 = v.w)
                float e = __shfl_down_sync(0xffffffffu, v[rb].x, 1, 16);
                if (laneHi) e = v[rb].w;
                m[rb][0] = fmaxf(m[rb][0], fabsf(wk - v[rb].y));
                m[rb][1] = fmaxf(m[rb][1], fabsf(wk - v[rb].z));
                m[rb][2] = fmaxf(m[rb][2], fabsf(wk - v[rb].w));
                m[rb][3] = fmaxf(m[rb][3], fabsf(wk - e));
            }
        } else {
#pragma unroll
            for (int rb = 0; rb < 4; ++rb) {
                // cols j0-1..j0+2 ; j0-1 = prev lane's v.w (col -1 -> clamp 0 = v.x)
                float e = __shfl_up_sync(0xffffffffu, v[rb].w, 1, 16);
                if (laneLo) e = v[rb].x;
                m[rb][0] = fmaxf(m[rb][0], fabsf(wk - e));
                m[rb][1] = fmaxf(m[rb][1], fabsf(wk - v[rb].x));
                m[rb][2] = fmaxf(m[rb][2], fabsf(wk - v[rb].y));
                m[rb][3] = fmaxf(m[rb][3], fabsf(wk - v[rb].z));
            }
        }
    };

    // Software-pipelined k loop: loads for k+1 in flight while consuming k.
    float4 va[4], vb[4];
    load4(va, 0);
    load4(vb, 1);
    consume(va, 0);
    load4(va, 2);
    consume(vb, 1);
    load4(vb, 3);
    consume(va, 2);
    consume(vb, 3);

    // Epilogue: bias + streaming float4 stores (contiguous per lane).
    float4* po = reinterpret_cast<float4*>(out + (size_t)blk * (HW * HW)) + r0 * 16 + lane16;
#pragma unroll
    for (int rb = 0; rb < 4; ++rb) {
        __stcs(po + rb * 16 * 16,
               make_float4(m[rb][0] + bs, m[rb][1] + bs, m[rb][2] + bs, m[rb][3] + bs));
    }
}

extern "C" void kernel_launch(void* const* d_in, const int* in_sizes, int n_in,
                              void* d_out, int out_size) {
    const float* x       = (const float*)d_in[0];
    const float* weights = (const float*)d_in[1];
    const float* bias    = (const float*)d_in[2];
    const int*   conn    = (const int*)d_in[3];
    float*       out     = (float*)d_out;

    const int B = in_sizes[0] / (CIN * HW * HW);   // 32
    lp_conv_bt_kernel<<<B * COUT, 256>>>(x, weights, bias, conn, out);
}